// round 12
// baseline (speedup 1.0000x reference)
#include <cuda_runtime.h>
#include <cuda_fp16.h>
#include <cstdint>

#define F_IN  512
#define F_OUT 256
#define MAX_N 100000
#define MAX_E 3200000

// ---------------- device scratch -------------------------------------------
__device__ __half g_supportH[(size_t)MAX_N * F_OUT];        // X @ W  (fp16, 51 MB)
__device__ int    g_count[MAX_N];
__device__ int    g_rowptr[MAX_N + 1];
__device__ int    g_wofs[MAX_N];
__device__ int2   g_edges[MAX_E];

// ---------------- PTX helpers ----------------------------------------------
__device__ __forceinline__ uint32_t smem_u32(const void* p) {
    uint32_t a;
    asm("{ .reg .u64 t; cvta.to.shared.u64 t, %1; cvt.u32.u64 %0, t; }"
        : "=r"(a) : "l"(p));
    return a;
}

#define LDSM_X4(r0, r1, r2, r3, addr) \
    asm volatile("ldmatrix.sync.aligned.m8n8.x4.shared.b16 {%0,%1,%2,%3}, [%4];" \
                 : "=r"(r0), "=r"(r1), "=r"(r2), "=r"(r3) : "r"(addr))

#define LDSM_X4_T(r0, r1, r2, r3, addr) \
    asm volatile("ldmatrix.sync.aligned.m8n8.x4.trans.shared.b16 {%0,%1,%2,%3}, [%4];" \
                 : "=r"(r0), "=r"(r1), "=r"(r2), "=r"(r3) : "r"(addr))

#define MMA_F16(d0, d1, d2, d3, a0, a1, a2, a3, b0, b1) \
    asm volatile("mma.sync.aligned.m16n8k16.row.col.f32.f16.f16.f32 " \
                 "{%0,%1,%2,%3}, {%4,%5,%6,%7}, {%8,%9}, {%0,%1,%2,%3};" \
                 : "+f"(d0), "+f"(d1), "+f"(d2), "+f"(d3) \
                 : "r"(a0), "r"(a1), "r"(a2), "r"(a3), "r"(b0), "r"(b1))

// split fp32x4 -> (hi f16x4, lo f16x4) packed as uint2 each
__device__ __forceinline__ void split4h(float4 v, uint2& h, uint2& l) {
    __half2 h01 = __floats2half2_rn(v.x, v.y);
    __half2 h23 = __floats2half2_rn(v.z, v.w);
    float2 f01 = __half22float2(h01);
    float2 f23 = __half22float2(h23);
    __half2 l01 = __floats2half2_rn(v.x - f01.x, v.y - f01.y);
    __half2 l23 = __floats2half2_rn(v.z - f23.x, v.w - f23.y);
    h.x = *(uint32_t*)&h01;  h.y = *(uint32_t*)&h23;
    l.x = *(uint32_t*)&l01;  l.y = *(uint32_t*)&l23;
}
__device__ __forceinline__ uint2 pack4h(float4 v) {
    __half2 p01 = __floats2half2_rn(v.x, v.y);
    __half2 p23 = __floats2half2_rn(v.z, v.w);
    uint2 r;
    r.x = *(uint32_t*)&p01;  r.y = *(uint32_t*)&p23;
    return r;
}

// ---------------------------------------------------------------------------
// Kernel 1: 2-term split-fp16 HMMA GEMM over ONE 128-col N-tile.
// support[:, ncol0:ncol0+128] = X @ W[:, ncol0:ncol0+128]
// CTA 128x128, 8 warps (4M x 2N), K-tile 32. 64 MMAs/k-tile.
// ---------------------------------------------------------------------------
#define SA_STR 40
#define SB_STR 136

__global__ __launch_bounds__(256, 2)
void gcn_mma_gemm(const float* __restrict__ A,   // [N, 512]
                  const float* __restrict__ W,   // [512, 256]
                  __half* __restrict__ C,        // [N, 256] fp16
                  int Nn, int ncol0) {
    __shared__ __align__(16) __half sAh[128 * SA_STR];
    __shared__ __align__(16) __half sAl[128 * SA_STR];
    __shared__ __align__(16) __half sB [32 * SB_STR];

    const int tid   = threadIdx.x;
    const int lane  = tid & 31;
    const int wid   = tid >> 5;
    const int warpM = wid & 3;
    const int warpN = wid >> 2;
    const int m0    = blockIdx.y * 128;
    const int n0    = ncol0;

    const uint32_t sAh_b = smem_u32(sAh);
    const uint32_t sAl_b = smem_u32(sAl);
    const uint32_t sB_b  = smem_u32(sB);

    float acc[2][8][4];
    #pragma unroll
    for (int i = 0; i < 2; i++)
        #pragma unroll
        for (int j = 0; j < 8; j++)
            #pragma unroll
            for (int k = 0; k < 4; k++) acc[i][j][k] = 0.0f;

    const int ar = tid >> 1;
    const int ac = (tid & 1) * 16;
    const int kr = tid >> 3;
    const int nc = (tid & 7) * 16;

    const uint32_t a_row  = (uint32_t)(warpM * 32 + (lane & 15));
    const uint32_t a_colb = (uint32_t)((lane >> 4) * 8);
    const uint32_t b_k    = (uint32_t)(((lane >> 3) & 1) * 8 + (lane & 7));
    const uint32_t b_n    = (uint32_t)(warpN * 64 + (lane >> 4) * 8);

    for (int kt = 0; kt < F_IN / 32; kt++) {
        const int k0 = kt * 32;
        {
            const int grow = m0 + ar;
            const float4* ap = (const float4*)(A + (size_t)grow * F_IN + k0 + ac);
            #pragma unroll
            for (int i = 0; i < 4; i++) {
                float4 v = (grow < Nn) ? __ldg(ap + i)
                                       : make_float4(0.f, 0.f, 0.f, 0.f);
                uint2 h, l;
                split4h(v, h, l);
                *(uint2*)(sAh + ar * SA_STR + ac + i * 4) = h;
                *(uint2*)(sAl + ar * SA_STR + ac + i * 4) = l;
            }
            const float4* bp = (const float4*)(W + (size_t)(k0 + kr) * F_OUT + n0 + nc);
            #pragma unroll
            for (int i = 0; i < 4; i++)
                *(uint2*)(sB + kr * SB_STR + nc + i * 4) = pack4h(__ldg(bp + i));
        }
        __syncthreads();

        #pragma unroll
        for (int ks = 0; ks < 2; ks++) {
            const uint32_t aoff0 = (a_row * SA_STR + (uint32_t)(ks * 16) + a_colb) * 2;
            const uint32_t aoff1 = aoff0 + 16 * SA_STR * 2;
            const uint32_t boffk = ((b_k + (uint32_t)(ks * 16)) * SB_STR + b_n) * 2;

            uint32_t ah[8], al[8], b[16];

            LDSM_X4(ah[0], ah[1], ah[2], ah[3], sAh_b + aoff0);
            LDSM_X4(ah[4], ah[5], ah[6], ah[7], sAh_b + aoff1);
            #pragma unroll
            for (int lg = 0; lg < 4; lg++)
                LDSM_X4_T(b[4 * lg], b[4 * lg + 1], b[4 * lg + 2], b[4 * lg + 3],
                          sB_b + boffk + (uint32_t)(lg * 16) * 2);

            #pragma unroll
            for (int mf = 0; mf < 2; mf++)
                #pragma unroll
                for (int nf = 0; nf < 8; nf++)
                    MMA_F16(acc[mf][nf][0], acc[mf][nf][1], acc[mf][nf][2], acc[mf][nf][3],
                            ah[4 * mf], ah[4 * mf + 1], ah[4 * mf + 2], ah[4 * mf + 3],
                            b[2 * nf], b[2 * nf + 1]);

            LDSM_X4(al[0], al[1], al[2], al[3], sAl_b + aoff0);
            LDSM_X4(al[4], al[5], al[6], al[7], sAl_b + aoff1);
            #pragma unroll
            for (int mf = 0; mf < 2; mf++)
                #pragma unroll
                for (int nf = 0; nf < 8; nf++)
                    MMA_F16(acc[mf][nf][0], acc[mf][nf][1], acc[mf][nf][2], acc[mf][nf][3],
                            al[4 * mf], al[4 * mf + 1], al[4 * mf + 2], al[4 * mf + 3],
                            b[2 * nf], b[2 * nf + 1]);
        }
        __syncthreads();
    }

    // ---- epilogue: fp16 stores ----
    const int g  = lane >> 2;
    const int tg = lane & 3;
    #pragma unroll
    for (int mf = 0; mf < 2; mf++) {
        #pragma unroll
        for (int nf = 0; nf < 8; nf++) {
            const int col  = n0 + warpN * 64 + nf * 8 + tg * 2;
            const int row0 = m0 + warpM * 32 + mf * 16 + g;
            const int row1 = row0 + 8;
            if (row0 < Nn)
                *(__half2*)(C + (size_t)row0 * F_OUT + col) =
                    __floats2half2_rn(acc[mf][nf][0], acc[mf][nf][1]);
            if (row1 < Nn)
                *(__half2*)(C + (size_t)row1 * F_OUT + col) =
                    __floats2half2_rn(acc[mf][nf][2], acc[mf][nf][3]);
        }
    }
}

// ---------------------------------------------------------------------------
// Kernel 2a: histogram of destination rows
// ---------------------------------------------------------------------------
__global__ __launch_bounds__(256)
void gcn_hist_kernel(const int* __restrict__ row, int E) {
    int e = blockIdx.x * blockDim.x + threadIdx.x;
    if (e < E) atomicAdd(&g_count[row[e]], 1);
}

// ---------------------------------------------------------------------------
// Kernel 2b: exclusive scan -> rowptr + cursors (single block)
// ---------------------------------------------------------------------------
__global__ __launch_bounds__(1024)
void gcn_scan_kernel(int n) {
    __shared__ int warp_sums[32];
    __shared__ int s_carry;
    const int tid = threadIdx.x, lane = tid & 31, wid = tid >> 5;
    if (tid == 0) s_carry = 0;
    __syncthreads();
    for (int base = 0; base < n; base += 1024) {
        int i = base + tid;
        int v = (i < n) ? g_count[i] : 0;
        int x = v;
        #pragma unroll
        for (int d = 1; d < 32; d <<= 1) {
            int y = __shfl_up_sync(0xffffffff, x, d);
            if (lane >= d) x += y;
        }
        if (lane == 31) warp_sums[wid] = x;
        __syncthreads();
        if (wid == 0) {
            int tsum = warp_sums[lane];
            #pragma unroll
            for (int d = 1; d < 32; d <<= 1) {
                int y = __shfl_up_sync(0xffffffff, tsum, d);
                if (lane >= d) tsum += y;
            }
            warp_sums[lane] = tsum;
        }
        __syncthreads();
        int warp_off = (wid > 0) ? warp_sums[wid - 1] : 0;
        int excl = s_carry + warp_off + x - v;
        if (i < n) { g_rowptr[i] = excl; g_wofs[i] = excl; }
        __syncthreads();
        if (tid == 0) s_carry += warp_sums[31];
        __syncthreads();
    }
    if (threadIdx.x == 0) g_rowptr[n] = s_carry;
}

// ---------------------------------------------------------------------------
// Kernel 2c: scatter edges into row-sorted order
// ---------------------------------------------------------------------------
__global__ __launch_bounds__(256)
void gcn_scatter_kernel(const int* __restrict__ row,
                        const int* __restrict__ col,
                        const float* __restrict__ val, int E) {
    int e = blockIdx.x * blockDim.x + threadIdx.x;
    if (e >= E) return;
    int r = row[e];
    int p = atomicAdd(&g_wofs[r], 1);
    g_edges[p] = make_int2(col[e], __float_as_int(val[e]));
}

// ---------------------------------------------------------------------------
// Kernel 3: CSR segment reduction over ONE 128-col half of fp16 support.
// GRID-STRIDE warp-per-row: launch grid sets SM footprint; BW-bound work
// tolerates a small grid (capped launch overlaps the GEMM without starving
// its CTA slots). Lane covers 4 cols (uint2 per edge). 8-edge unroll.
// ---------------------------------------------------------------------------
__device__ __forceinline__ void acc_edge2(float acc[4], uint2 v, float wv) {
    const __half2* h = (const __half2*)&v;
    float2 f0 = __half22float2(h[0]);
    float2 f1 = __half22float2(h[1]);
    acc[0] = fmaf(wv, f0.x, acc[0]);
    acc[1] = fmaf(wv, f0.y, acc[1]);
    acc[2] = fmaf(wv, f1.x, acc[2]);
    acc[3] = fmaf(wv, f1.y, acc[3]);
}

__global__ __launch_bounds__(256)
void gcn_csr_kernel(const __half* __restrict__ support,
                    const float* __restrict__ bias,
                    float* __restrict__ out, int N, int coff) {
    const int lane    = threadIdx.x & 31;
    const int warp0   = (blockIdx.x * blockDim.x + threadIdx.x) >> 5;
    const int nwarps  = (gridDim.x * blockDim.x) >> 5;

    const float4 bi = __ldg((const float4*)(bias + coff) + lane);

    for (int w = warp0; w < N; w += nwarps) {
        int s = g_rowptr[w];
        int e = g_rowptr[w + 1];

        float acc[4] = {0.f, 0.f, 0.f, 0.f};

        int i = s;
        for (; i + 8 <= e; i += 8) {
            int2  cv[8];
            uint2 v[8];
            #pragma unroll
            for (int u = 0; u < 8; u++) cv[u] = g_edges[i + u];
            #pragma unroll
            for (int u = 0; u < 8; u++)
                v[u] = __ldg((const uint2*)(support + (size_t)cv[u].x * F_OUT + coff) + lane);
            #pragma unroll
            for (int u = 0; u < 8; u++)
                acc_edge2(acc, v[u], __int_as_float(cv[u].y));
        }
        for (; i + 4 <= e; i += 4) {
            int2  cv[4];
            uint2 v[4];
            #pragma unroll
            for (int u = 0; u < 4; u++) cv[u] = g_edges[i + u];
            #pragma unroll
            for (int u = 0; u < 4; u++)
                v[u] = __ldg((const uint2*)(support + (size_t)cv[u].x * F_OUT + coff) + lane);
            #pragma unroll
            for (int u = 0; u < 4; u++)
                acc_edge2(acc, v[u], __int_as_float(cv[u].y));
        }
        for (; i < e; i++) {
            int2 cv = g_edges[i];
            uint2 v = __ldg((const uint2*)(support + (size_t)cv.x * F_OUT + coff) + lane);
            acc_edge2(acc, v, __int_as_float(cv.y));
        }

        float4 o;
        o.x = __fdiv_rn(rintf(acc[0] * 1000.0f), 1000.0f) + bi.x;
        o.y = __fdiv_rn(rintf(acc[1] * 1000.0f), 1000.0f) + bi.y;
        o.z = __fdiv_rn(rintf(acc[2] * 1000.0f), 1000.0f) + bi.z;
        o.w = __fdiv_rn(rintf(acc[3] * 1000.0f), 1000.0f) + bi.w;

        *(float4*)(out + (size_t)w * F_OUT + coff + lane * 4) = o;
    }
}

// ---------------------------------------------------------------------------
// Launch — three-way pipeline:
//   s1: CSR build chain (hidden under GEMM0)
//   main: GEMM(cols 0-127) -> GEMM(cols 128-255) -> CSR(cols 128-255, full grid)
//   s2: CSR(cols 0-127, CAPPED grid), overlapping GEMM(cols 128-255)
// ---------------------------------------------------------------------------
extern "C" void kernel_launch(void* const* d_in, const int* in_sizes, int n_in,
                              void* d_out, int out_size) {
    const float* x        = (const float*)d_in[0];
    const float* weight   = (const float*)d_in[1];
    const float* bias     = (const float*)d_in[2];
    const float* edge_val = (const float*)d_in[3];
    const int*   row      = (const int*)d_in[4];
    const int*   col      = (const int*)d_in[5];
    float*       out      = (float*)d_out;

    const int N = in_sizes[0] / F_IN;
    const int E = in_sizes[3];

    __half* support;
    cudaGetSymbolAddress((void**)&support, g_supportH);
    int* count_ptr;
    cudaGetSymbolAddress((void**)&count_ptr, g_count);

    static cudaStream_t s1 = nullptr, s2 = nullptr;
    static cudaEvent_t ev_fork = nullptr, ev_join = nullptr;
    static cudaEvent_t ev_g0 = nullptr, ev_c0 = nullptr;
    static bool init_done = false;
    if (!init_done) {
        cudaStreamCreateWithFlags(&s1, cudaStreamNonBlocking);
        cudaStreamCreateWithFlags(&s2, cudaStreamNonBlocking);
        cudaEventCreateWithFlags(&ev_fork, cudaEventDisableTiming);
        cudaEventCreateWithFlags(&ev_join, cudaEventDisableTiming);
        cudaEventCreateWithFlags(&ev_g0, cudaEventDisableTiming);
        cudaEventCreateWithFlags(&ev_c0, cudaEventDisableTiming);
        init_done = true;
    }

    const int eblocks        = (E + 255) / 256;
    const int csr_blocks_full = (N * 32 + 255) / 256;  // warp per row, one pass
    const int csr_blocks_cap  = 296;                    // 2 CTAs/SM: leaves slots for GEMM
    const dim3 gemm_grid(1, (N + 127) / 128);

    // fork: CSR build chain on s1
    cudaEventRecord(ev_fork, 0);
    cudaStreamWaitEvent(s1, ev_fork, 0);

    cudaMemsetAsync(count_ptr, 0, (size_t)N * sizeof(int), s1);
    gcn_hist_kernel<<<eblocks, 256, 0, s1>>>(row, E);
    gcn_scan_kernel<<<1, 1024, 0, s1>>>(N);
    gcn_scatter_kernel<<<eblocks, 256, 0, s1>>>(row, col, edge_val, E);
    cudaEventRecord(ev_join, s1);

    // GEMM half 0 (cols 0-127) on main
    gcn_mma_gemm<<<gemm_grid, 256>>>(x, weight, support, N, 0);
    cudaEventRecord(ev_g0, 0);

    // GEMM half 1 (cols 128-255) on main
    gcn_mma_gemm<<<gemm_grid, 256>>>(x, weight, support, N, 128);

    // CSR half 0 on s2 (CAPPED grid): needs GEMM0 + sorted edges; overlaps GEMM1
    cudaStreamWaitEvent(s2, ev_g0, 0);
    cudaStreamWaitEvent(s2, ev_join, 0);
    gcn_csr_kernel<<<csr_blocks_cap, 256, 0, s2>>>(support, bias, out, N, 0);
    cudaEventRecord(ev_c0, s2);

    // CSR half 1 on main (full grid): needs GEMM1 (stream order) + sorted edges
    cudaStreamWaitEvent(0, ev_join, 0);
    gcn_csr_kernel<<<csr_blocks_full, 256>>>(support, bias, out, N, 128);

    // join s2 back into main
    cudaStreamWaitEvent(0, ev_c0, 0);
}

// round 13
// speedup vs baseline: 1.2601x; 1.2601x over previous
#include <cuda_runtime.h>
#include <cuda_fp16.h>
#include <cstdint>

#define F_IN  512
#define F_OUT 256
#define MAX_N 100000
#define MAX_E 3200000

// ---------------- device scratch -------------------------------------------
__device__ __half g_supportH[(size_t)MAX_N * F_OUT];        // X @ W  (fp16, 51 MB)
__device__ int    g_count[MAX_N];
__device__ int    g_rowptr[MAX_N + 1];
__device__ int    g_wofs[MAX_N];
__device__ int2   g_edges[MAX_E];

// ---------------- PTX helpers ----------------------------------------------
__device__ __forceinline__ uint32_t smem_u32(const void* p) {
    uint32_t a;
    asm("{ .reg .u64 t; cvta.to.shared.u64 t, %1; cvt.u32.u64 %0, t; }"
        : "=r"(a) : "l"(p));
    return a;
}

#define LDSM_X4(r0, r1, r2, r3, addr) \
    asm volatile("ldmatrix.sync.aligned.m8n8.x4.shared.b16 {%0,%1,%2,%3}, [%4];" \
                 : "=r"(r0), "=r"(r1), "=r"(r2), "=r"(r3) : "r"(addr))

#define LDSM_X4_T(r0, r1, r2, r3, addr) \
    asm volatile("ldmatrix.sync.aligned.m8n8.x4.trans.shared.b16 {%0,%1,%2,%3}, [%4];" \
                 : "=r"(r0), "=r"(r1), "=r"(r2), "=r"(r3) : "r"(addr))

#define MMA_F16(d0, d1, d2, d3, a0, a1, a2, a3, b0, b1) \
    asm volatile("mma.sync.aligned.m16n8k16.row.col.f32.f16.f16.f32 " \
                 "{%0,%1,%2,%3}, {%4,%5,%6,%7}, {%8,%9}, {%0,%1,%2,%3};" \
                 : "+f"(d0), "+f"(d1), "+f"(d2), "+f"(d3) \
                 : "r"(a0), "r"(a1), "r"(a2), "r"(a3), "r"(b0), "r"(b1))

// split fp32x4 -> (hi f16x4, lo f16x4) packed as uint2 each
__device__ __forceinline__ void split4h(float4 v, uint2& h, uint2& l) {
    __half2 h01 = __floats2half2_rn(v.x, v.y);
    __half2 h23 = __floats2half2_rn(v.z, v.w);
    float2 f01 = __half22float2(h01);
    float2 f23 = __half22float2(h23);
    __half2 l01 = __floats2half2_rn(v.x - f01.x, v.y - f01.y);
    __half2 l23 = __floats2half2_rn(v.z - f23.x, v.w - f23.y);
    h.x = *(uint32_t*)&h01;  h.y = *(uint32_t*)&h23;
    l.x = *(uint32_t*)&l01;  l.y = *(uint32_t*)&l23;
}
__device__ __forceinline__ uint2 pack4h(float4 v) {
    __half2 p01 = __floats2half2_rn(v.x, v.y);
    __half2 p23 = __floats2half2_rn(v.z, v.w);
    uint2 r;
    r.x = *(uint32_t*)&p01;  r.y = *(uint32_t*)&p23;
    return r;
}

// ---------------------------------------------------------------------------
// Kernel 1: 2-term split-fp16 HMMA GEMM over ONE 128-col N-tile.
// support[:, ncol0:ncol0+128] = X @ W[:, ncol0:ncol0+128]
// CTA 128x128, 8 warps (4M x 2N), K-tile 32. 64 MMAs/k-tile.
// ---------------------------------------------------------------------------
#define SA_STR 40
#define SB_STR 136

__global__ __launch_bounds__(256, 2)
void gcn_mma_gemm(const float* __restrict__ A,   // [N, 512]
                  const float* __restrict__ W,   // [512, 256]
                  __half* __restrict__ C,        // [N, 256] fp16
                  int Nn, int ncol0) {
    __shared__ __align__(16) __half sAh[128 * SA_STR];
    __shared__ __align__(16) __half sAl[128 * SA_STR];
    __shared__ __align__(16) __half sB [32 * SB_STR];

    const int tid   = threadIdx.x;
    const int lane  = tid & 31;
    const int wid   = tid >> 5;
    const int warpM = wid & 3;
    const int warpN = wid >> 2;
    const int m0    = blockIdx.y * 128;
    const int n0    = ncol0;

    const uint32_t sAh_b = smem_u32(sAh);
    const uint32_t sAl_b = smem_u32(sAl);
    const uint32_t sB_b  = smem_u32(sB);

    float acc[2][8][4];
    #pragma unroll
    for (int i = 0; i < 2; i++)
        #pragma unroll
        for (int j = 0; j < 8; j++)
            #pragma unroll
            for (int k = 0; k < 4; k++) acc[i][j][k] = 0.0f;

    const int ar = tid >> 1;
    const int ac = (tid & 1) * 16;
    const int kr = tid >> 3;
    const int nc = (tid & 7) * 16;

    const uint32_t a_row  = (uint32_t)(warpM * 32 + (lane & 15));
    const uint32_t a_colb = (uint32_t)((lane >> 4) * 8);
    const uint32_t b_k    = (uint32_t)(((lane >> 3) & 1) * 8 + (lane & 7));
    const uint32_t b_n    = (uint32_t)(warpN * 64 + (lane >> 4) * 8);

    for (int kt = 0; kt < F_IN / 32; kt++) {
        const int k0 = kt * 32;
        {
            const int grow = m0 + ar;
            const float4* ap = (const float4*)(A + (size_t)grow * F_IN + k0 + ac);
            #pragma unroll
            for (int i = 0; i < 4; i++) {
                float4 v = (grow < Nn) ? __ldg(ap + i)
                                       : make_float4(0.f, 0.f, 0.f, 0.f);
                uint2 h, l;
                split4h(v, h, l);
                *(uint2*)(sAh + ar * SA_STR + ac + i * 4) = h;
                *(uint2*)(sAl + ar * SA_STR + ac + i * 4) = l;
            }
            const float4* bp = (const float4*)(W + (size_t)(k0 + kr) * F_OUT + n0 + nc);
            #pragma unroll
            for (int i = 0; i < 4; i++)
                *(uint2*)(sB + kr * SB_STR + nc + i * 4) = pack4h(__ldg(bp + i));
        }
        __syncthreads();

        #pragma unroll
        for (int ks = 0; ks < 2; ks++) {
            const uint32_t aoff0 = (a_row * SA_STR + (uint32_t)(ks * 16) + a_colb) * 2;
            const uint32_t aoff1 = aoff0 + 16 * SA_STR * 2;
            const uint32_t boffk = ((b_k + (uint32_t)(ks * 16)) * SB_STR + b_n) * 2;

            uint32_t ah[8], al[8], b[16];

            LDSM_X4(ah[0], ah[1], ah[2], ah[3], sAh_b + aoff0);
            LDSM_X4(ah[4], ah[5], ah[6], ah[7], sAh_b + aoff1);
            #pragma unroll
            for (int lg = 0; lg < 4; lg++)
                LDSM_X4_T(b[4 * lg], b[4 * lg + 1], b[4 * lg + 2], b[4 * lg + 3],
                          sB_b + boffk + (uint32_t)(lg * 16) * 2);

            #pragma unroll
            for (int mf = 0; mf < 2; mf++)
                #pragma unroll
                for (int nf = 0; nf < 8; nf++)
                    MMA_F16(acc[mf][nf][0], acc[mf][nf][1], acc[mf][nf][2], acc[mf][nf][3],
                            ah[4 * mf], ah[4 * mf + 1], ah[4 * mf + 2], ah[4 * mf + 3],
                            b[2 * nf], b[2 * nf + 1]);

            LDSM_X4(al[0], al[1], al[2], al[3], sAl_b + aoff0);
            LDSM_X4(al[4], al[5], al[6], al[7], sAl_b + aoff1);
            #pragma unroll
            for (int mf = 0; mf < 2; mf++)
                #pragma unroll
                for (int nf = 0; nf < 8; nf++)
                    MMA_F16(acc[mf][nf][0], acc[mf][nf][1], acc[mf][nf][2], acc[mf][nf][3],
                            al[4 * mf], al[4 * mf + 1], al[4 * mf + 2], al[4 * mf + 3],
                            b[2 * nf], b[2 * nf + 1]);
        }
        __syncthreads();
    }

    // ---- epilogue: fp16 stores ----
    const int g  = lane >> 2;
    const int tg = lane & 3;
    #pragma unroll
    for (int mf = 0; mf < 2; mf++) {
        #pragma unroll
        for (int nf = 0; nf < 8; nf++) {
            const int col  = n0 + warpN * 64 + nf * 8 + tg * 2;
            const int row0 = m0 + warpM * 32 + mf * 16 + g;
            const int row1 = row0 + 8;
            if (row0 < Nn)
                *(__half2*)(C + (size_t)row0 * F_OUT + col) =
                    __floats2half2_rn(acc[mf][nf][0], acc[mf][nf][1]);
            if (row1 < Nn)
                *(__half2*)(C + (size_t)row1 * F_OUT + col) =
                    __floats2half2_rn(acc[mf][nf][2], acc[mf][nf][3]);
        }
    }
}

// ---------------------------------------------------------------------------
// Kernel 2a: histogram of destination rows
// ---------------------------------------------------------------------------
__global__ __launch_bounds__(256)
void gcn_hist_kernel(const int* __restrict__ row, int E) {
    int e = blockIdx.x * blockDim.x + threadIdx.x;
    if (e < E) atomicAdd(&g_count[row[e]], 1);
}

// ---------------------------------------------------------------------------
// Kernel 2b: exclusive scan -> rowptr + cursors (single block)
// ---------------------------------------------------------------------------
__global__ __launch_bounds__(1024)
void gcn_scan_kernel(int n) {
    __shared__ int warp_sums[32];
    __shared__ int s_carry;
    const int tid = threadIdx.x, lane = tid & 31, wid = tid >> 5;
    if (tid == 0) s_carry = 0;
    __syncthreads();
    for (int base = 0; base < n; base += 1024) {
        int i = base + tid;
        int v = (i < n) ? g_count[i] : 0;
        int x = v;
        #pragma unroll
        for (int d = 1; d < 32; d <<= 1) {
            int y = __shfl_up_sync(0xffffffff, x, d);
            if (lane >= d) x += y;
        }
        if (lane == 31) warp_sums[wid] = x;
        __syncthreads();
        if (wid == 0) {
            int tsum = warp_sums[lane];
            #pragma unroll
            for (int d = 1; d < 32; d <<= 1) {
                int y = __shfl_up_sync(0xffffffff, tsum, d);
                if (lane >= d) tsum += y;
            }
            warp_sums[lane] = tsum;
        }
        __syncthreads();
        int warp_off = (wid > 0) ? warp_sums[wid - 1] : 0;
        int excl = s_carry + warp_off + x - v;
        if (i < n) { g_rowptr[i] = excl; g_wofs[i] = excl; }
        __syncthreads();
        if (tid == 0) s_carry += warp_sums[31];
        __syncthreads();
    }
    if (threadIdx.x == 0) g_rowptr[n] = s_carry;
}

// ---------------------------------------------------------------------------
// Kernel 2c: scatter edges into row-sorted order
// ---------------------------------------------------------------------------
__global__ __launch_bounds__(256)
void gcn_scatter_kernel(const int* __restrict__ row,
                        const int* __restrict__ col,
                        const float* __restrict__ val, int E) {
    int e = blockIdx.x * blockDim.x + threadIdx.x;
    if (e >= E) return;
    int r = row[e];
    int p = atomicAdd(&g_wofs[r], 1);
    g_edges[p] = make_int2(col[e], __float_as_int(val[e]));
}

// ---------------------------------------------------------------------------
// Kernel 3: CSR segment reduction over ONE 128-col half of fp16 support.
// Warp-per-row, FULL grid (R11 post-mortem: capping starves the per-row
// latency chains, not BW — full parallelism is required). Grid-stride form
// kept but executes exactly once per warp at full grid.
// ---------------------------------------------------------------------------
__device__ __forceinline__ void acc_edge2(float acc[4], uint2 v, float wv) {
    const __half2* h = (const __half2*)&v;
    float2 f0 = __half22float2(h[0]);
    float2 f1 = __half22float2(h[1]);
    acc[0] = fmaf(wv, f0.x, acc[0]);
    acc[1] = fmaf(wv, f0.y, acc[1]);
    acc[2] = fmaf(wv, f1.x, acc[2]);
    acc[3] = fmaf(wv, f1.y, acc[3]);
}

__global__ __launch_bounds__(256)
void gcn_csr_kernel(const __half* __restrict__ support,
                    const float* __restrict__ bias,
                    float* __restrict__ out, int N, int coff) {
    const int lane    = threadIdx.x & 31;
    const int warp0   = (blockIdx.x * blockDim.x + threadIdx.x) >> 5;
    const int nwarps  = (gridDim.x * blockDim.x) >> 5;

    const float4 bi = __ldg((const float4*)(bias + coff) + lane);

    for (int w = warp0; w < N; w += nwarps) {
        int s = g_rowptr[w];
        int e = g_rowptr[w + 1];

        float acc[4] = {0.f, 0.f, 0.f, 0.f};

        int i = s;
        for (; i + 8 <= e; i += 8) {
            int2  cv[8];
            uint2 v[8];
            #pragma unroll
            for (int u = 0; u < 8; u++) cv[u] = g_edges[i + u];
            #pragma unroll
            for (int u = 0; u < 8; u++)
                v[u] = __ldg((const uint2*)(support + (size_t)cv[u].x * F_OUT + coff) + lane);
            #pragma unroll
            for (int u = 0; u < 8; u++)
                acc_edge2(acc, v[u], __int_as_float(cv[u].y));
        }
        for (; i + 4 <= e; i += 4) {
            int2  cv[4];
            uint2 v[4];
            #pragma unroll
            for (int u = 0; u < 4; u++) cv[u] = g_edges[i + u];
            #pragma unroll
            for (int u = 0; u < 4; u++)
                v[u] = __ldg((const uint2*)(support + (size_t)cv[u].x * F_OUT + coff) + lane);
            #pragma unroll
            for (int u = 0; u < 4; u++)
                acc_edge2(acc, v[u], __int_as_float(cv[u].y));
        }
        for (; i < e; i++) {
            int2 cv = g_edges[i];
            uint2 v = __ldg((const uint2*)(support + (size_t)cv.x * F_OUT + coff) + lane);
            acc_edge2(acc, v, __int_as_float(cv.y));
        }

        float4 o;
        o.x = __fdiv_rn(rintf(acc[0] * 1000.0f), 1000.0f) + bi.x;
        o.y = __fdiv_rn(rintf(acc[1] * 1000.0f), 1000.0f) + bi.y;
        o.z = __fdiv_rn(rintf(acc[2] * 1000.0f), 1000.0f) + bi.z;
        o.w = __fdiv_rn(rintf(acc[3] * 1000.0f), 1000.0f) + bi.w;

        *(float4*)(out + (size_t)w * F_OUT + coff + lane * 4) = o;
    }
}

// ---------------------------------------------------------------------------
// Launch — pipeline with stream priorities:
//   s1      : CSR build chain (hidden under GEMM0)
//   s_hi    : GEMM0 -> GEMM1 -> CSR1   (HIGH priority: wins CTA scheduling)
//   s_lo    : CSR0 (full grid, LOW priority), overlapping GEMM1
// ---------------------------------------------------------------------------
extern "C" void kernel_launch(void* const* d_in, const int* in_sizes, int n_in,
                              void* d_out, int out_size) {
    const float* x        = (const float*)d_in[0];
    const float* weight   = (const float*)d_in[1];
    const float* bias     = (const float*)d_in[2];
    const float* edge_val = (const float*)d_in[3];
    const int*   row      = (const int*)d_in[4];
    const int*   col      = (const int*)d_in[5];
    float*       out      = (float*)d_out;

    const int N = in_sizes[0] / F_IN;
    const int E = in_sizes[3];

    __half* support;
    cudaGetSymbolAddress((void**)&support, g_supportH);
    int* count_ptr;
    cudaGetSymbolAddress((void**)&count_ptr, g_count);

    static cudaStream_t s1 = nullptr, s_lo = nullptr, s_hi = nullptr;
    static cudaEvent_t ev_fork = nullptr, ev_join = nullptr;
    static cudaEvent_t ev_g0 = nullptr, ev_c0 = nullptr, ev_c1 = nullptr;
    static bool init_done = false;
    if (!init_done) {
        int prio_lo, prio_hi;
        cudaDeviceGetStreamPriorityRange(&prio_lo, &prio_hi);
        cudaStreamCreateWithFlags(&s1, cudaStreamNonBlocking);
        cudaStreamCreateWithPriority(&s_lo, cudaStreamNonBlocking, prio_lo);
        cudaStreamCreateWithPriority(&s_hi, cudaStreamNonBlocking, prio_hi);
        cudaEventCreateWithFlags(&ev_fork, cudaEventDisableTiming);
        cudaEventCreateWithFlags(&ev_join, cudaEventDisableTiming);
        cudaEventCreateWithFlags(&ev_g0, cudaEventDisableTiming);
        cudaEventCreateWithFlags(&ev_c0, cudaEventDisableTiming);
        cudaEventCreateWithFlags(&ev_c1, cudaEventDisableTiming);
        init_done = true;
    }

    const int eblocks    = (E + 255) / 256;
    const int csr_blocks = (N * 32 + 255) / 256;   // full warp-per-row grid
    const dim3 gemm_grid(1, (N + 127) / 128);

    // fork from the caller's stream
    cudaEventRecord(ev_fork, 0);
    cudaStreamWaitEvent(s1, ev_fork, 0);
    cudaStreamWaitEvent(s_hi, ev_fork, 0);

    // CSR build chain on s1
    cudaMemsetAsync(count_ptr, 0, (size_t)N * sizeof(int), s1);
    gcn_hist_kernel<<<eblocks, 256, 0, s1>>>(row, E);
    gcn_scan_kernel<<<1, 1024, 0, s1>>>(N);
    gcn_scatter_kernel<<<eblocks, 256, 0, s1>>>(row, col, edge_val, E);
    cudaEventRecord(ev_join, s1);

    // GEMM half 0 (cols 0-127) on s_hi
    gcn_mma_gemm<<<gemm_grid, 256, 0, s_hi>>>(x, weight, support, N, 0);
    cudaEventRecord(ev_g0, s_hi);

    // GEMM half 1 (cols 128-255) on s_hi
    gcn_mma_gemm<<<gemm_grid, 256, 0, s_hi>>>(x, weight, support, N, 128);

    // CSR half 0 on s_lo (LOW priority, full grid): overlaps GEMM1
    cudaStreamWaitEvent(s_lo, ev_g0, 0);
    cudaStreamWaitEvent(s_lo, ev_join, 0);
    gcn_csr_kernel<<<csr_blocks, 256, 0, s_lo>>>(support, bias, out, N, 0);
    cudaEventRecord(ev_c0, s_lo);

    // CSR half 1 on s_hi: after GEMM1 (stream order) + sorted edges
    cudaStreamWaitEvent(s_hi, ev_join, 0);
    gcn_csr_kernel<<<csr_blocks, 256, 0, s_hi>>>(support, bias, out, N, 128);
    cudaEventRecord(ev_c1, s_hi);

    // join both tails back into the caller's stream
    cudaStreamWaitEvent(0, ev_c0, 0);
    cudaStreamWaitEvent(0, ev_c1, 0);
}